// round 1
// baseline (speedup 1.0000x reference)
#include <cuda_runtime.h>
#include <cstdint>

#define DIM 1024
#define NO  256
#define NR  512
#define BM  128
#define BN  128
#define BK  32
#define AS  36            // A smem row stride (floats): 32 + 4 pad -> conflict-free frag loads
#define BS  136           // B smem row stride (floats): 128 + 8 pad -> conflict-free frag loads
#define ATILE (BM*AS)     // 4608 floats
#define BTILE (BK*BS)     // 4352 floats
#define SMEM_BYTES ((2*ATILE + 2*BTILE)*4)   // 71680 B, double-buffered

__device__ __forceinline__ uint32_t f2tf(float x){
    uint32_t u; asm("cvt.rna.tf32.f32 %0, %1;" : "=r"(u) : "f"(x)); return u;
}
__device__ __forceinline__ void cpa16(uint32_t s, const void* g){
    asm volatile("cp.async.cg.shared.global [%0], [%1], 16;" :: "r"(s), "l"(g));
}
__device__ __forceinline__ void cpcommit(){ asm volatile("cp.async.commit_group;"); }
__device__ __forceinline__ void cpwait0(){ asm volatile("cp.async.wait_group 0;"); }

__device__ __forceinline__ void mma8(float* c, const uint32_t* a, const uint32_t* b){
    asm volatile("mma.sync.aligned.m16n8k8.row.col.f32.tf32.tf32.f32 "
        "{%0,%1,%2,%3}, {%4,%5,%6,%7}, {%8,%9}, {%0,%1,%2,%3};"
        : "+f"(c[0]), "+f"(c[1]), "+f"(c[2]), "+f"(c[3])
        : "r"(a[0]), "r"(a[1]), "r"(a[2]), "r"(a[3]), "r"(b[0]), "r"(b[1]));
}

// MODE 1: A = [obj | attr],       K=2048, residual=attr
// MODE 2: A = [obj[s]|rela|obj[o]], K=3072, residual=rela, *mask
template<int MODE>
__global__ __launch_bounds__(256)
void gnn_gemm(const float* __restrict__ obj, const float* __restrict__ xres,
              const int* __restrict__ edges, const float* __restrict__ masks,
              const float* __restrict__ W, const float* __restrict__ bias,
              float* __restrict__ out)
{
    constexpr int K  = (MODE==1) ? 2048 : 3072;
    constexpr int KT = K / BK;

    extern __shared__ float sm[];
    float* sA = sm;                 // [2][ATILE]
    float* sB = sm + 2*ATILE;       // [2][BTILE]
    __shared__ int sS[BM], sO[BM];
    __shared__ int sI32;

    const int  tid  = threadIdx.x;
    const int  nblk = blockIdx.x;
    const long row0 = (long)blockIdx.y * BM;

    if (MODE == 2) {
        if (tid < 32) {
            // sniff edges layout: int64 -> every odd 32-bit word is a zero high-word
            int w = edges[2*tid + 1];
            unsigned bal = __ballot_sync(0xffffffffu, w != 0);
            if (tid == 0) sI32 = (bal != 0);
        }
        __syncthreads();
        if (tid < BM) {
            long r  = row0 + tid;            // global rela row
            int  bb = (int)(r >> 9);         // r / NR
            int  s, o;
            if (sI32) { s = edges[2*r];   o = edges[2*r + 1]; }
            else      { s = edges[4*r];   o = edges[4*r + 2]; }
            sS[tid] = bb*NO + s;
            sO[tid] = bb*NO + o;
        }
        __syncthreads();
    }

    const int lrow = tid >> 3;          // 0..31  (A row within 32-row slab)
    const int lcol = (tid & 7) * 4;     // float col, 16B chunks
    const uint32_t sAb = (uint32_t)__cvta_generic_to_shared(sA);
    const uint32_t sBb = (uint32_t)__cvta_generic_to_shared(sB);

    auto load_tile = [&](int kt, int buf){
        const int k0  = kt * BK;
        const int seg = k0 >> 10;       // segment of concat (k-tile never straddles)
        const int kin = k0 & 1023;
        const uint32_t abase = sAb + (uint32_t)(buf*ATILE)*4u;
        #pragma unroll
        for (int i = 0; i < 4; i++) {
            const int r = lrow + 32*i;
            const float* src;
            if (MODE == 1) {
                const long grow = row0 + r;
                src = (seg == 0 ? obj : xres) + grow*DIM + kin + lcol;
            } else {
                if (seg == 0)      src = obj  + (long)sS[r]*DIM + kin + lcol;
                else if (seg == 1) src = xres + (row0 + r)*DIM  + kin + lcol;
                else               src = obj  + (long)sO[r]*DIM + kin + lcol;
            }
            cpa16(abase + (uint32_t)(r*AS + lcol)*4u, src);
        }
        const uint32_t bbase = sBb + (uint32_t)(buf*BTILE)*4u;
        const int bk  = tid >> 3;         // 0..31 (k row)
        const int bn0 = (tid & 7) * 16;   // 16 floats per thread
        const float* wsrc = W + (long)(k0 + bk)*DIM + (long)nblk*BN + bn0;
        #pragma unroll
        for (int j = 0; j < 4; j++)
            cpa16(bbase + (uint32_t)(bk*BS + bn0 + j*4)*4u, wsrc + j*4);
    };

    float acc[4][4][4];
    #pragma unroll
    for (int a = 0; a < 4; a++)
        #pragma unroll
        for (int b = 0; b < 4; b++)
            #pragma unroll
            for (int c = 0; c < 4; c++) acc[a][b][c] = 0.f;

    const int wid = tid >> 5, lane = tid & 31;
    const int warpM = wid >> 2, warpN = wid & 3;   // 2 x 4 warp grid, warp tile 64x32
    const int grp = lane >> 2, qd = lane & 3;

    load_tile(0, 0);
    cpcommit();

    for (int kt = 0; kt < KT; kt++) {
        cpwait0();
        __syncthreads();
        if (kt + 1 < KT) load_tile(kt + 1, (kt + 1) & 1);
        cpcommit();

        const float* At = sA + (kt & 1)*ATILE;
        const float* Bt = sB + (kt & 1)*BTILE;
        #pragma unroll
        for (int k8 = 0; k8 < 4; k8++) {
            const int kb = k8 * 8;
            uint32_t af[4][4], bf[4][2];
            #pragma unroll
            for (int mt = 0; mt < 4; mt++) {
                const int r = warpM*64 + mt*16 + grp;
                af[mt][0] = f2tf(At[ r      *AS + kb + qd    ]);
                af[mt][1] = f2tf(At[(r + 8) *AS + kb + qd    ]);
                af[mt][2] = f2tf(At[ r      *AS + kb + qd + 4]);
                af[mt][3] = f2tf(At[(r + 8) *AS + kb + qd + 4]);
            }
            #pragma unroll
            for (int nt = 0; nt < 4; nt++) {
                const int c = warpN*32 + nt*8 + grp;
                bf[nt][0] = f2tf(Bt[(kb + qd    )*BS + c]);
                bf[nt][1] = f2tf(Bt[(kb + qd + 4)*BS + c]);
            }
            #pragma unroll
            for (int mt = 0; mt < 4; mt++)
                #pragma unroll
                for (int nt = 0; nt < 4; nt++)
                    mma8(acc[mt][nt], af[mt], bf[nt]);
        }
    }

    // Epilogue: +bias, relu, +residual, (mask), store
    const long colBase = (long)nblk * BN;
    #pragma unroll
    for (int mt = 0; mt < 4; mt++) {
        const long r0 = row0 + warpM*64 + mt*16 + grp;
        #pragma unroll
        for (int nt = 0; nt < 4; nt++) {
            const long c  = colBase + warpN*32 + nt*8 + 2*qd;
            const float2 bs = *(const float2*)(bias + c);
            #pragma unroll
            for (int h = 0; h < 2; h++) {
                const long rr = r0 + 8*h;
                const float2 res = *(const float2*)(xres + rr*DIM + c);
                float v0 = acc[mt][nt][2*h + 0] + bs.x;
                float v1 = acc[mt][nt][2*h + 1] + bs.y;
                v0 = fmaxf(v0, 0.f) + res.x;
                v1 = fmaxf(v1, 0.f) + res.y;
                if (MODE == 2) { const float m = masks[rr]; v0 *= m; v1 *= m; }
                *(float2*)(out + rr*DIM + c) = make_float2(v0, v1);
            }
        }
    }
}

extern "C" void kernel_launch(void* const* d_in, const int* in_sizes, int n_in,
                              void* d_out, int out_size)
{
    const float* obj   = (const float*)d_in[0];
    const float* attr  = (const float*)d_in[1];
    const float* rela  = (const float*)d_in[2];
    const int*   edges = (const int*)  d_in[3];
    const float* masks = (const float*)d_in[4];
    const float* Wa    = (const float*)d_in[5];
    const float* ba    = (const float*)d_in[6];
    const float* Wr    = (const float*)d_in[7];
    const float* br    = (const float*)d_in[8];

    const int    B     = in_sizes[0] / (NO * DIM);
    const size_t objN  = (size_t)B * NO * DIM;
    float* out = (float*)d_out;

    // output layout: [new_obj | new_attr | new_rela]
    cudaMemcpyAsync(out, obj, objN * sizeof(float), cudaMemcpyDeviceToDevice);

    cudaFuncSetAttribute(gnn_gemm<1>, cudaFuncAttributeMaxDynamicSharedMemorySize, SMEM_BYTES);
    cudaFuncSetAttribute(gnn_gemm<2>, cudaFuncAttributeMaxDynamicSharedMemorySize, SMEM_BYTES);

    const int M1 = B * NO;   // 32768
    const int M2 = B * NR;   // 65536
    gnn_gemm<1><<<dim3(DIM/BN, M1/BM), 256, SMEM_BYTES>>>(
        obj, attr, nullptr, nullptr, Wa, ba, out + objN);
    gnn_gemm<2><<<dim3(DIM/BN, M2/BM), 256, SMEM_BYTES>>>(
        obj, rela, edges, masks, Wr, br, out + 2*objN);
}

// round 5
// speedup vs baseline: 1.0947x; 1.0947x over previous
#include <cuda_runtime.h>
#include <cstdint>

#define DIM 1024
#define NO  256
#define NR  512
#define BM  128
#define BN  128
#define BK  32
#define AS  36            // A smem row stride (floats): conflict-free frag loads (banks 4r+qd)
#define BS  136           // B smem row stride (floats): conflict-free frag loads (banks 8qd+grp)
#define ATILE (BM*AS)     // 4608 floats
#define BTILE (BK*BS)     // 4352 floats
#define SMEM_BYTES ((2*ATILE + 2*BTILE)*4)   // 71680 B double-buffered -> 2 CTAs/SM

__device__ __forceinline__ void cpa16(uint32_t s, const void* g){
    asm volatile("cp.async.cg.shared.global [%0], [%1], 16;" :: "r"(s), "l"(g));
}
__device__ __forceinline__ void cpcommit(){ asm volatile("cp.async.commit_group;"); }
__device__ __forceinline__ void cpwait0(){ asm volatile("cp.async.wait_group 0;"); }

__device__ __forceinline__ void mma8(float* c, const uint32_t* a, const uint32_t* b){
    asm volatile("mma.sync.aligned.m16n8k8.row.col.f32.tf32.tf32.f32 "
        "{%0,%1,%2,%3}, {%4,%5,%6,%7}, {%8,%9}, {%0,%1,%2,%3};"
        : "+f"(c[0]), "+f"(c[1]), "+f"(c[2]), "+f"(c[3])
        : "r"(a[0]), "r"(a[1]), "r"(a[2]), "r"(a[3]), "r"(b[0]), "r"(b[1]));
}

// MODE 1: A = [obj | attr],         K=2048, residual=attr
// MODE 2: A = [obj[s]|rela|obj[o]], K=3072, residual=rela, *mask
// 128 threads = 4 warps (2x2), warp tile 64x64, CTA tile 128x128.
template<int MODE>
__global__ __launch_bounds__(128)
void gnn_gemm(const float* __restrict__ obj, const float* __restrict__ xres,
              const int* __restrict__ edges, const float* __restrict__ masks,
              const float* __restrict__ W, const float* __restrict__ bias,
              float* __restrict__ out)
{
    constexpr int K  = (MODE==1) ? 2048 : 3072;
    constexpr int KT = K / BK;

    extern __shared__ float sm[];
    float* sA = sm;                 // [2][ATILE]
    float* sB = sm + 2*ATILE;       // [2][BTILE]
    __shared__ int sS[BM], sO[BM];
    __shared__ int sI32;

    const int  tid  = threadIdx.x;
    const int  nblk = blockIdx.x;
    const long row0 = (long)blockIdx.y * BM;

    if (MODE == 2) {
        if (tid < 32) {
            // sniff edges layout: int64 -> every odd 32-bit word is a zero high-word
            int w = edges[2*tid + 1];
            unsigned bal = __ballot_sync(0xffffffffu, w != 0);
            if (tid == 0) sI32 = (bal != 0);
        }
        __syncthreads();
        if (tid < BM) {
            long r  = row0 + tid;            // global rela row
            int  bb = (int)(r >> 9);         // r / NR
            int  s, o;
            if (sI32) { s = edges[2*r];   o = edges[2*r + 1]; }
            else      { s = edges[4*r];   o = edges[4*r + 2]; }
            sS[tid] = bb*NO + s;
            sO[tid] = bb*NO + o;
        }
        __syncthreads();
    }

    const int lrow = tid >> 3;          // 0..15  (A row within 16-row slab)
    const int lcol = (tid & 7) * 4;     // float col, 16B chunks
    const uint32_t sAb = (uint32_t)__cvta_generic_to_shared(sA);
    const uint32_t sBb = (uint32_t)__cvta_generic_to_shared(sB);

    auto load_tile = [&](int kt, int buf){
        const int k0  = kt * BK;
        const int seg = k0 >> 10;       // segment of concat (k-tile never straddles)
        const int kin = k0 & 1023;
        const uint32_t abase = sAb + (uint32_t)(buf*ATILE)*4u;
        #pragma unroll
        for (int i = 0; i < 8; i++) {
            const int r = lrow + 16*i;
            const float* src;
            if (MODE == 1) {
                const long grow = row0 + r;
                src = (seg == 0 ? obj : xres) + grow*DIM + kin + lcol;
            } else {
                if (seg == 0)      src = obj  + (long)sS[r]*DIM + kin + lcol;
                else if (seg == 1) src = xres + (row0 + r)*DIM  + kin + lcol;
                else               src = obj  + (long)sO[r]*DIM + kin + lcol;
            }
            cpa16(abase + (uint32_t)(r*AS + lcol)*4u, src);
        }
        const uint32_t bbase = sBb + (uint32_t)(buf*BTILE)*4u;
        const int bk  = tid >> 2;         // 0..31 (k row)
        const int bn0 = (tid & 3) * 32;   // 32 floats per thread
        const float* wsrc = W + (long)(k0 + bk)*DIM + (long)nblk*BN + bn0;
        #pragma unroll
        for (int j = 0; j < 8; j++)
            cpa16(bbase + (uint32_t)(bk*BS + bn0 + j*4)*4u, wsrc + j*4);
    };

    float acc[4][8][4];
    #pragma unroll
    for (int a = 0; a < 4; a++)
        #pragma unroll
        for (int b = 0; b < 8; b++)
            #pragma unroll
            for (int c = 0; c < 4; c++) acc[a][b][c] = 0.f;

    const int wid = tid >> 5, lane = tid & 31;
    const int warpM = wid >> 1, warpN = wid & 1;   // 2 x 2 warp grid, warp tile 64x64
    const int grp = lane >> 2, qd = lane & 3;

    load_tile(0, 0);
    cpcommit();

    for (int kt = 0; kt < KT; kt++) {
        cpwait0();
        __syncthreads();
        if (kt + 1 < KT) load_tile(kt + 1, (kt + 1) & 1);
        cpcommit();

        // reinterpret smem floats as raw tf32 bits (HW ignores low 13 mantissa bits)
        const uint32_t* At = (const uint32_t*)(sA + (kt & 1)*ATILE);
        const uint32_t* Bt = (const uint32_t*)(sB + (kt & 1)*BTILE);
        #pragma unroll
        for (int k8 = 0; k8 < 4; k8++) {
            const int kb = k8 * 8;
            uint32_t af[4][4], bf[8][2];
            #pragma unroll
            for (int mt = 0; mt < 4; mt++) {
                const int r = warpM*64 + mt*16 + grp;
                af[mt][0] = At[ r      *AS + kb + qd    ];
                af[mt][1] = At[(r + 8) *AS + kb + qd    ];
                af[mt][2] = At[ r      *AS + kb + qd + 4];
                af[mt][3] = At[(r + 8) *AS + kb + qd + 4];
            }
            #pragma unroll
            for (int nt = 0; nt < 8; nt++) {
                const int c = warpN*64 + nt*8 + grp;
                bf[nt][0] = Bt[(kb + qd    )*BS + c];
                bf[nt][1] = Bt[(kb + qd + 4)*BS + c];
            }
            #pragma unroll
            for (int mt = 0; mt < 4; mt++)
                #pragma unroll
                for (int nt = 0; nt < 8; nt++)
                    mma8(acc[mt][nt], af[mt], bf[nt]);
        }
    }

    // Epilogue: +bias, relu, +residual, (mask), store
    const long colBase = (long)nblk * BN;
    #pragma unroll
    for (int mt = 0; mt < 4; mt++) {
        const long r0 = row0 + warpM*64 + mt*16 + grp;
        #pragma unroll
        for (int nt = 0; nt < 8; nt++) {
            const long c  = colBase + warpN*64 + nt*8 + 2*qd;
            const float2 bs = *(const float2*)(bias + c);
            #pragma unroll
            for (int h = 0; h < 2; h++) {
                const long rr = r0 + 8*h;
                const float2 res = *(const float2*)(xres + rr*DIM + c);
                float v0 = acc[mt][nt][2*h + 0] + bs.x;
                float v1 = acc[mt][nt][2*h + 1] + bs.y;
                v0 = fmaxf(v0, 0.f) + res.x;
                v1 = fmaxf(v1, 0.f) + res.y;
                if (MODE == 2) { const float m = masks[rr]; v0 *= m; v1 *= m; }
                *(float2*)(out + rr*DIM + c) = make_float2(v0, v1);
            }
        }
    }
}

extern "C" void kernel_launch(void* const* d_in, const int* in_sizes, int n_in,
                              void* d_out, int out_size)
{
    const float* obj   = (const float*)d_in[0];
    const float* attr  = (const float*)d_in[1];
    const float* rela  = (const float*)d_in[2];
    const int*   edges = (const int*)  d_in[3];
    const float* masks = (const float*)d_in[4];
    const float* Wa    = (const float*)d_in[5];
    const float* ba    = (const float*)d_in[6];
    const float* Wr    = (const float*)d_in[7];
    const float* br    = (const float*)d_in[8];

    const int    B     = in_sizes[0] / (NO * DIM);
    const size_t objN  = (size_t)B * NO * DIM;
    float* out = (float*)d_out;

    // output layout: [new_obj | new_attr | new_rela]
    cudaMemcpyAsync(out, obj, objN * sizeof(float), cudaMemcpyDeviceToDevice);

    cudaFuncSetAttribute(gnn_gemm<1>, cudaFuncAttributeMaxDynamicSharedMemorySize, SMEM_BYTES);
    cudaFuncSetAttribute(gnn_gemm<2>, cudaFuncAttributeMaxDynamicSharedMemorySize, SMEM_BYTES);

    const int M1 = B * NO;   // 32768
    const int M2 = B * NR;   // 65536
    gnn_gemm<1><<<dim3(DIM/BN, M1/BM), 128, SMEM_BYTES>>>(
        obj, attr, nullptr, nullptr, Wa, ba, out + objN);
    gnn_gemm<2><<<dim3(DIM/BN, M2/BM), 128, SMEM_BYTES>>>(
        obj, rela, edges, masks, Wr, br, out + 2*objN);
}

// round 7
// speedup vs baseline: 2.4446x; 2.2331x over previous
#include <cuda_runtime.h>
#include <cuda_fp16.h>
#include <cstdint>

#define DIM 1024
#define NO  256
#define NR  512
#define BMAX 128
#define BM  128
#define BN  128
#define BK  64            // fp16 k per stage = 4 x k16 steps
#define STAGES 3
#define A_BYTES (BM*BK*2)                 // 16 KB
#define B_BYTES (BK*BN*2)                 // 16 KB
#define STAGE_BYTES (A_BYTES + B_BYTES)   // 32 KB
#define SMEM_BYTES (STAGES*STAGE_BYTES)   // 96 KB

// fp16 converted operands (static scratch; no allocation)
__device__ __half g_obj_h [BMAX*NO*DIM];
__device__ __half g_attr_h[BMAX*NO*DIM];
__device__ __half g_rela_h[BMAX*NR*DIM];
__device__ __half g_Wa_h  [2048*DIM];
__device__ __half g_Wr_h  [3072*DIM];

// ---------- helpers ----------
__device__ __forceinline__ void cpa16(uint32_t s, const void* g){
    asm volatile("cp.async.cg.shared.global [%0], [%1], 16;" :: "r"(s), "l"(g));
}
__device__ __forceinline__ void cpcommit(){ asm volatile("cp.async.commit_group;"); }
template<int N> __device__ __forceinline__ void cpwait(){
    asm volatile("cp.async.wait_group %0;" :: "n"(N));
}
__device__ __forceinline__ void ldmA(uint32_t* r, uint32_t a){
    asm volatile("ldmatrix.sync.aligned.m8n8.x4.shared.b16 {%0,%1,%2,%3}, [%4];"
        : "=r"(r[0]), "=r"(r[1]), "=r"(r[2]), "=r"(r[3]) : "r"(a));
}
__device__ __forceinline__ void ldmBT(uint32_t* r, uint32_t a){
    asm volatile("ldmatrix.sync.aligned.m8n8.x4.trans.shared.b16 {%0,%1,%2,%3}, [%4];"
        : "=r"(r[0]), "=r"(r[1]), "=r"(r[2]), "=r"(r[3]) : "r"(a));
}
__device__ __forceinline__ void mma16(float* c, const uint32_t* a, const uint32_t* b){
    asm volatile("mma.sync.aligned.m16n8k16.row.col.f32.f16.f16.f32 "
        "{%0,%1,%2,%3}, {%4,%5,%6,%7}, {%8,%9}, {%0,%1,%2,%3};"
        : "+f"(c[0]), "+f"(c[1]), "+f"(c[2]), "+f"(c[3])
        : "r"(a[0]), "r"(a[1]), "r"(a[2]), "r"(a[3]), "r"(b[0]), "r"(b[1]));
}

// ---------- fp32 -> fp16 conversion prepass (vectorized, RNE) ----------
__global__ void f2h(const float4* __restrict__ src, uint2* __restrict__ dst, long n4){
    const long stride = (long)gridDim.x * blockDim.x;
    for (long i = (long)blockIdx.x * blockDim.x + threadIdx.x; i < n4; i += stride) {
        const float4 v = src[i];
        const __half2 h0 = __floats2half2_rn(v.x, v.y);
        const __half2 h1 = __floats2half2_rn(v.z, v.w);
        uint2 o;
        o.x = *(const uint32_t*)&h0;
        o.y = *(const uint32_t*)&h1;
        dst[i] = o;
    }
}

// ---------- fp16 mma.sync GEMM ----------
// MODE 1: A = [obj | attr],         K=2048, residual=attr
// MODE 2: A = [obj[s]|rela|obj[o]], K=3072, residual=rela, *mask
// 128 threads = 4 warps (2x2), warp tile 64x64, CTA tile 128x128.
template<int MODE>
__global__ __launch_bounds__(128)
void gnn_gemm(const __half* __restrict__ objh, const __half* __restrict__ xh,
              const float* __restrict__ xres,
              const int* __restrict__ edges, const float* __restrict__ masks,
              const __half* __restrict__ Wh, const float* __restrict__ bias,
              float* __restrict__ out)
{
    constexpr int K  = (MODE==1) ? 2048 : 3072;
    constexpr int KT = K / BK;

    extern __shared__ char smem[];
    __shared__ int sS[BM], sO[BM];
    __shared__ int sI32;

    const uint32_t smem_base = (uint32_t)__cvta_generic_to_shared(smem);
    const int tid  = threadIdx.x;
    const int nblk = blockIdx.x;
    const long row0 = (long)blockIdx.y * BM;
    const long n0   = (long)nblk * BN;

    if (MODE == 2) {
        if (tid < 32) {
            // sniff edges layout: int64 -> every odd 32-bit word is a zero high-word
            int w = edges[2*tid + 1];
            unsigned bal = __ballot_sync(0xffffffffu, w != 0);
            if (tid == 0) sI32 = (bal != 0);
        }
        __syncthreads();
        if (tid < BM) {
            long r  = row0 + tid;
            int  bb = (int)(r >> 9);         // r / NR
            int  s, o;
            if (sI32) { s = edges[2*r]; o = edges[2*r + 1]; }
            else      { s = edges[4*r]; o = edges[4*r + 2]; }
            sS[tid] = bb*NO + s;
            sO[tid] = bb*NO + o;
        }
        __syncthreads();
    }

    auto load_stage = [&](int j){
        const int st = j % STAGES;
        const uint32_t a_s = smem_base + st*STAGE_BYTES;
        const uint32_t b_s = a_s + A_BYTES;
        const int k0  = j * BK;              // fp16 element offset in concat-K
        const int seg = k0 >> 10;            // 64 | 1024 -> never straddles
        const int kin = k0 & 1023;
        // A: 128 rows x 128B (64 fp16); 1024 x 16B chunks; 8 per thread
        #pragma unroll
        for (int i = 0; i < 8; i++) {
            const int chunk = tid + i*128;
            const int r = chunk >> 3;        // row 0..127
            const int c = chunk & 7;         // 16B chunk in row
            const __half* src;
            if (MODE == 1) {
                src = (seg == 0 ? objh : xh) + (row0 + r)*DIM + kin + c*8;
            } else {
                if (seg == 0)      src = objh + (long)sS[r]*DIM + kin + c*8;
                else if (seg == 1) src = xh   + (row0 + r)*DIM  + kin + c*8;
                else               src = objh + (long)sO[r]*DIM + kin + c*8;
            }
            cpa16(a_s + (uint32_t)(r*128 + ((c ^ r) & 7)*16), src);
        }
        // B: 64 k-rows x 256B (128 fp16); 1024 x 16B chunks; 8 per thread
        #pragma unroll
        for (int i = 0; i < 8; i++) {
            const int chunk = tid + i*128;
            const int r = chunk >> 4;        // k row 0..63
            const int c = chunk & 15;        // 16B chunk in row
            const __half* src = Wh + (long)(k0 + r)*DIM + n0 + c*8;
            cpa16(b_s + (uint32_t)(r*256 + (c & 8)*16 + ((c ^ r) & 7)*16), src);
        }
        cpcommit();
    };

    float acc[4][8][4];
    #pragma unroll
    for (int a = 0; a < 4; a++)
        #pragma unroll
        for (int b = 0; b < 8; b++)
            #pragma unroll
            for (int c = 0; c < 4; c++) acc[a][b][c] = 0.f;

    const int wid = tid >> 5, lane = tid & 31;
    const int warpM = wid >> 1, warpN = wid & 1;   // 2x2 warps, warp tile 64x64
    const int grp = lane >> 2, qd = lane & 3;

    // ldmatrix lane-address components
    const int l8  = lane & 7;
    const int lm8 = (lane & 8) ? 8 : 0;            // second 8x8 block (rows +8)
    const int l16 = (lane >> 4) & 1;               // third/fourth block (cols +8)

    load_stage(0);
    load_stage(1);

    for (int kt = 0; kt < KT; kt++) {
        cpwait<STAGES-2>();
        __syncthreads();

        const int st = kt % STAGES;
        const uint32_t a_s = smem_base + st*STAGE_BYTES;
        const uint32_t b_s = a_s + A_BYTES;

        #pragma unroll
        for (int ks = 0; ks < BK/16; ks++) {
            // A frags: 4 m16 tiles
            uint32_t af[4][4];
            #pragma unroll
            for (int mt = 0; mt < 4; mt++) {
                const int mr = warpM*64 + mt*16 + l8 + lm8;
                const int ch = ks*2 + l16;                      // 16B chunk (k8 step)
                ldmA(af[mt], a_s + (uint32_t)(mr*128 + ((ch ^ mr) & 7)*16));
            }
            // B frags: 4 n16 groups (-> 8 n8 tiles), transposed from k-major W
            uint32_t bf[8][2];
            #pragma unroll
            for (int ng = 0; ng < 4; ng++) {
                const int kr = ks*16 + l8 + lm8;                // stored k row
                const int c  = warpN*8 + ng*2 + l16;            // 16B chunk (n8 group)
                uint32_t t[4];
                ldmBT(t, b_s + (uint32_t)(kr*256 + (c & 8)*16 + ((c ^ kr) & 7)*16));
                bf[2*ng+0][0] = t[0]; bf[2*ng+0][1] = t[1];
                bf[2*ng+1][0] = t[2]; bf[2*ng+1][1] = t[3];
            }
            #pragma unroll
            for (int mt = 0; mt < 4; mt++)
                #pragma unroll
                for (int nt = 0; nt < 8; nt++)
                    mma16(acc[mt][nt], af[mt], bf[nt]);
        }

        const int jn = kt + STAGES - 1;
        if (jn < KT) load_stage(jn);
    }

    // Epilogue: +bias, relu, +residual(fp32), (mask), store
    #pragma unroll
    for (int mt = 0; mt < 4; mt++) {
        const long r0 = row0 + warpM*64 + mt*16 + grp;
        #pragma unroll
        for (int nt = 0; nt < 8; nt++) {
            const long c  = n0 + warpN*64 + nt*8 + 2*qd;
            const float2 bs = *(const float2*)(bias + c);
            #pragma unroll
            for (int h = 0; h < 2; h++) {
                const long rr = r0 + 8*h;
                const float2 res = *(const float2*)(xres + rr*DIM + c);
                float v0 = acc[mt][nt][2*h + 0] + bs.x;
                float v1 = acc[mt][nt][2*h + 1] + bs.y;
                v0 = fmaxf(v0, 0.f) + res.x;
                v1 = fmaxf(v1, 0.f) + res.y;
                if (MODE == 2) { const float m = masks[rr]; v0 *= m; v1 *= m; }
                *(float2*)(out + rr*DIM + c) = make_float2(v0, v1);
            }
        }
    }
}

extern "C" void kernel_launch(void* const* d_in, const int* in_sizes, int n_in,
                              void* d_out, int out_size)
{
    const float* obj   = (const float*)d_in[0];
    const float* attr  = (const float*)d_in[1];
    const float* rela  = (const float*)d_in[2];
    const int*   edges = (const int*)  d_in[3];
    const float* masks = (const float*)d_in[4];
    const float* Wa    = (const float*)d_in[5];
    const float* ba    = (const float*)d_in[6];
    const float* Wr    = (const float*)d_in[7];
    const float* br    = (const float*)d_in[8];

    const int    B     = in_sizes[0] / (NO * DIM);
    const size_t objN  = (size_t)B * NO * DIM;
    const size_t relaN = (size_t)B * NR * DIM;
    float* out = (float*)d_out;

    __half *objh, *attrh, *relah, *wah, *wrh;
    cudaGetSymbolAddress((void**)&objh,  g_obj_h);
    cudaGetSymbolAddress((void**)&attrh, g_attr_h);
    cudaGetSymbolAddress((void**)&relah, g_rela_h);
    cudaGetSymbolAddress((void**)&wah,   g_Wa_h);
    cudaGetSymbolAddress((void**)&wrh,   g_Wr_h);

    // fp32 -> fp16 prepass
    auto conv = [&](const float* s, __half* d, size_t n){
        const long n4 = (long)(n / 4);
        int grid = (int)((n4 + 511) / 512);
        if (grid > 8192) grid = 8192;
        f2h<<<grid, 512>>>((const float4*)s, (uint2*)d, n4);
    };
    conv(obj,  objh,  objN);
    conv(attr, attrh, objN);
    conv(rela, relah, relaN);
    conv(Wa,   wah,   (size_t)2048*DIM);
    conv(Wr,   wrh,   (size_t)3072*DIM);

    // output layout: [new_obj | new_attr | new_rela]
    cudaMemcpyAsync(out, obj, objN * sizeof(float), cudaMemcpyDeviceToDevice);

    cudaFuncSetAttribute(gnn_gemm<1>, cudaFuncAttributeMaxDynamicSharedMemorySize, SMEM_BYTES);
    cudaFuncSetAttribute(gnn_gemm<2>, cudaFuncAttributeMaxDynamicSharedMemorySize, SMEM_BYTES);

    const int M1 = B * NO;   // 32768
    const int M2 = B * NR;   // 65536
    gnn_gemm<1><<<dim3(DIM/BN, M1/BM), 128, SMEM_BYTES>>>(
        objh, attrh, attr, nullptr, nullptr, wah, ba, out + objN);
    gnn_gemm<2><<<dim3(DIM/BN, M2/BM), 128, SMEM_BYTES>>>(
        objh, relah, rela, edges, masks, wrh, br, out + 2*objN);
}

// round 9
// speedup vs baseline: 2.6804x; 1.0965x over previous
#include <cuda_runtime.h>
#include <cuda_fp16.h>
#include <cstdint>

#define DIM 1024
#define NO  256
#define NR  512
#define BMAX 128
#define BM  128
#define BN  128
#define BK  64            // fp16 k per stage = 4 x k16 steps
#define STAGES 3
#define A_BYTES (BM*BK*2)                 // 16 KB
#define B_BYTES (BK*BN*2)                 // 16 KB
#define STAGE_BYTES (A_BYTES + B_BYTES)   // 32 KB
#define SMEM_BYTES (STAGES*STAGE_BYTES)   // 96 KB -> 2 CTAs/SM

// fp16 converted operands (static scratch; no allocation)
__device__ __half g_obj_h [BMAX*NO*DIM];
__device__ __half g_attr_h[BMAX*NO*DIM];
__device__ __half g_rela_h[BMAX*NR*DIM];
__device__ __half g_Wa_h  [2048*DIM];
__device__ __half g_Wr_h  [3072*DIM];

// ---------- helpers ----------
__device__ __forceinline__ void cpa16(uint32_t s, const void* g){
    asm volatile("cp.async.cg.shared.global [%0], [%1], 16;" :: "r"(s), "l"(g));
}
__device__ __forceinline__ void cpcommit(){ asm volatile("cp.async.commit_group;"); }
template<int N> __device__ __forceinline__ void cpwait(){
    asm volatile("cp.async.wait_group %0;" :: "n"(N));
}
__device__ __forceinline__ void ldmA(uint32_t* r, uint32_t a){
    asm volatile("ldmatrix.sync.aligned.m8n8.x4.shared.b16 {%0,%1,%2,%3}, [%4];"
        : "=r"(r[0]), "=r"(r[1]), "=r"(r[2]), "=r"(r[3]) : "r"(a));
}
__device__ __forceinline__ void ldmBT(uint32_t* r, uint32_t a){
    asm volatile("ldmatrix.sync.aligned.m8n8.x4.trans.shared.b16 {%0,%1,%2,%3}, [%4];"
        : "=r"(r[0]), "=r"(r[1]), "=r"(r[2]), "=r"(r[3]) : "r"(a));
}
__device__ __forceinline__ void mma16(float* c, const uint32_t* a, const uint32_t* b){
    asm volatile("mma.sync.aligned.m16n8k16.row.col.f32.f16.f16.f32 "
        "{%0,%1,%2,%3}, {%4,%5,%6,%7}, {%8,%9}, {%0,%1,%2,%3};"
        : "+f"(c[0]), "+f"(c[1]), "+f"(c[2]), "+f"(c[3])
        : "r"(a[0]), "r"(a[1]), "r"(a[2]), "r"(a[3]), "r"(b[0]), "r"(b[1]));
}

// ---------- fp32 -> fp16 conversion prepass (vectorized, RNE) ----------
__global__ void f2h(const float4* __restrict__ src, uint2* __restrict__ dst, long n4){
    const long i = (long)blockIdx.x * blockDim.x + threadIdx.x;
    if (i >= n4) return;
    const float4 v = src[i];
    const __half2 h0 = __floats2half2_rn(v.x, v.y);
    const __half2 h1 = __floats2half2_rn(v.z, v.w);
    uint2 o;
    o.x = *(const uint32_t*)&h0;
    o.y = *(const uint32_t*)&h1;
    dst[i] = o;
}

// ---------- fp16 mma.sync GEMM ----------
// MODE 1: A = [obj | attr],         K=2048, residual=attr
// MODE 2: A = [obj[s]|rela|obj[o]], K=3072, residual=rela, *mask
// 256 threads = 8 warps (4x2), warp tile 32x64, CTA tile 128x128.
template<int MODE>
__global__ __launch_bounds__(256, 2)
void gnn_gemm(const __half* __restrict__ objh, const __half* __restrict__ xh,
              const float* __restrict__ xres,
              const int* __restrict__ edges, const float* __restrict__ masks,
              const __half* __restrict__ Wh, const float* __restrict__ bias,
              float* __restrict__ out)
{
    constexpr int K  = (MODE==1) ? 2048 : 3072;
    constexpr int KT = K / BK;

    extern __shared__ char smem[];
    __shared__ int sS[BM], sO[BM];
    __shared__ int sI32;

    const uint32_t smem_base = (uint32_t)__cvta_generic_to_shared(smem);
    const int tid  = threadIdx.x;
    const int nblk = blockIdx.x;
    const long row0 = (long)blockIdx.y * BM;
    const long n0   = (long)nblk * BN;

    if (MODE == 2) {
        if (tid < 32) {
            // sniff edges layout: int64 -> every odd 32-bit word is a zero high-word
            int w = edges[2*tid + 1];
            unsigned bal = __ballot_sync(0xffffffffu, w != 0);
            if (tid == 0) sI32 = (bal != 0);
        }
        __syncthreads();
        if (tid < BM) {
            long r  = row0 + tid;
            int  bb = (int)(r >> 9);         // r / NR
            int  s, o;
            if (sI32) { s = edges[2*r]; o = edges[2*r + 1]; }
            else      { s = edges[4*r]; o = edges[4*r + 2]; }
            sS[tid] = bb*NO + s;
            sO[tid] = bb*NO + o;
        }
        __syncthreads();
    }

    auto load_stage = [&](int j){
        const int st = j % STAGES;
        const uint32_t a_s = smem_base + st*STAGE_BYTES;
        const uint32_t b_s = a_s + A_BYTES;
        const int k0  = j * BK;              // fp16 element offset in concat-K
        const int seg = k0 >> 10;            // 64 | 1024 -> never straddles
        const int kin = k0 & 1023;
        // A: 128 rows x 128B (64 fp16); 1024 x 16B chunks; 4 per thread
        #pragma unroll
        for (int i = 0; i < 4; i++) {
            const int chunk = tid + i*256;
            const int r = chunk >> 3;        // row 0..127
            const int c = chunk & 7;         // 16B chunk in row
            const __half* src;
            if (MODE == 1) {
                src = (seg == 0 ? objh : xh) + (row0 + r)*DIM + kin + c*8;
            } else {
                if (seg == 0)      src = objh + (long)sS[r]*DIM + kin + c*8;
                else if (seg == 1) src = xh   + (row0 + r)*DIM  + kin + c*8;
                else               src = objh + (long)sO[r]*DIM + kin + c*8;
            }
            cpa16(a_s + (uint32_t)(r*128 + ((c ^ r) & 7)*16), src);
        }
        // B: 64 k-rows x 256B (128 fp16); 1024 x 16B chunks; 4 per thread
        #pragma unroll
        for (int i = 0; i < 4; i++) {
            const int chunk = tid + i*256;
            const int r = chunk >> 4;        // k row 0..63
            const int c = chunk & 15;        // 16B chunk in row
            const __half* src = Wh + (long)(k0 + r)*DIM + n0 + c*8;
            cpa16(b_s + (uint32_t)(r*256 + (c & 8)*16 + ((c ^ r) & 7)*16), src);
        }
        cpcommit();
    };

    float acc[2][8][4];
    #pragma unroll
    for (int a = 0; a < 2; a++)
        #pragma unroll
        for (int b = 0; b < 8; b++)
            #pragma unroll
            for (int c = 0; c < 4; c++) acc[a][b][c] = 0.f;

    const int wid = tid >> 5, lane = tid & 31;
    const int warpM = wid >> 1, warpN = wid & 1;   // 4x2 warps, warp tile 32x64
    const int grp = lane >> 2, qd = lane & 3;

    // ldmatrix lane-address components
    const int l8  = lane & 7;
    const int lm8 = (lane & 8) ? 8 : 0;            // second 8x8 block (rows +8)
    const int l16 = (lane >> 4) & 1;               // third/fourth block (cols +8)

    load_stage(0);
    load_stage(1);

    for (int kt = 0; kt < KT; kt++) {
        cpwait<STAGES-2>();
        __syncthreads();

        const int st = kt % STAGES;
        const uint32_t a_s = smem_base + st*STAGE_BYTES;
        const uint32_t b_s = a_s + A_BYTES;

        #pragma unroll
        for (int ks = 0; ks < BK/16; ks++) {
            // A frags: 2 m16 tiles
            uint32_t af[2][4];
            #pragma unroll
            for (int mt = 0; mt < 2; mt++) {
                const int mr = warpM*32 + mt*16 + l8 + lm8;
                const int ch = ks*2 + l16;                      // 16B chunk (k8 step)
                ldmA(af[mt], a_s + (uint32_t)(mr*128 + ((ch ^ mr) & 7)*16));
            }
            // B frags: 4 n16 groups (-> 8 n8 tiles), transposed from k-major W
            uint32_t bf[8][2];
            #pragma unroll
            for (int ng = 0; ng < 4; ng++) {
                const int kr = ks*16 + l8 + lm8;                // stored k row
                const int c  = warpN*8 + ng*2 + l16;            // 16B chunk (n8 group)
                uint32_t t[4];
                ldmBT(t, b_s + (uint32_t)(kr*256 + (c & 8)*16 + ((c ^ kr) & 7)*16));
                bf[2*ng+0][0] = t[0]; bf[2*ng+0][1] = t[1];
                bf[2*ng+1][0] = t[2]; bf[2*ng+1][1] = t[3];
            }
            #pragma unroll
            for (int mt = 0; mt < 2; mt++)
                #pragma unroll
                for (int nt = 0; nt < 8; nt++)
                    mma16(acc[mt][nt], af[mt], bf[nt]);
        }

        const int jn = kt + STAGES - 1;
        if (jn < KT) load_stage(jn);
    }

    // Epilogue: +bias, relu, +residual(fp32), (mask), store
    #pragma unroll
    for (int mt = 0; mt < 2; mt++) {
        const long r0 = row0 + warpM*32 + mt*16 + grp;
        #pragma unroll
        for (int nt = 0; nt < 8; nt++) {
            const long c  = n0 + warpN*64 + nt*8 + 2*qd;
            const float2 bs = *(const float2*)(bias + c);
            #pragma unroll
            for (int h = 0; h < 2; h++) {
                const long rr = r0 + 8*h;
                const float2 res = *(const float2*)(xres + rr*DIM + c);
                float v0 = acc[mt][nt][2*h + 0] + bs.x;
                float v1 = acc[mt][nt][2*h + 1] + bs.y;
                v0 = fmaxf(v0, 0.f) + res.x;
                v1 = fmaxf(v1, 0.f) + res.y;
                if (MODE == 2) { const float m = masks[rr]; v0 *= m; v1 *= m; }
                *(float2*)(out + rr*DIM + c) = make_float2(v0, v1);
            }
        }
    }
}

extern "C" void kernel_launch(void* const* d_in, const int* in_sizes, int n_in,
                              void* d_out, int out_size)
{
    const float* obj   = (const float*)d_in[0];
    const float* attr  = (const float*)d_in[1];
    const float* rela  = (const float*)d_in[2];
    const int*   edges = (const int*)  d_in[3];
    const float* masks = (const float*)d_in[4];
    const float* Wa    = (const float*)d_in[5];
    const float* ba    = (const float*)d_in[6];
    const float* Wr    = (const float*)d_in[7];
    const float* br    = (const float*)d_in[8];

    const int    B     = in_sizes[0] / (NO * DIM);
    const size_t objN  = (size_t)B * NO * DIM;
    const size_t relaN = (size_t)B * NR * DIM;
    float* out = (float*)d_out;

    __half *objh, *attrh, *relah, *wah, *wrh;
    cudaGetSymbolAddress((void**)&objh,  g_obj_h);
    cudaGetSymbolAddress((void**)&attrh, g_attr_h);
    cudaGetSymbolAddress((void**)&relah, g_rela_h);
    cudaGetSymbolAddress((void**)&wah,   g_Wa_h);
    cudaGetSymbolAddress((void**)&wrh,   g_Wr_h);

    // fp32 -> fp16 prepass (one element per thread, exact grid)
    auto conv = [&](const float* s, __half* d, size_t n){
        const long n4 = (long)(n / 4);
        const int grid = (int)((n4 + 255) / 256);
        f2h<<<grid, 256>>>((const float4*)s, (uint2*)d, n4);
    };
    conv(obj,  objh,  objN);
    conv(attr, attrh, objN);
    conv(rela, relah, relaN);
    conv(Wa,   wah,   (size_t)2048*DIM);
    conv(Wr,   wrh,   (size_t)3072*DIM);

    // output layout: [new_obj | new_attr | new_rela]
    cudaMemcpyAsync(out, obj, objN * sizeof(float), cudaMemcpyDeviceToDevice);

    cudaFuncSetAttribute(gnn_gemm<1>, cudaFuncAttributeMaxDynamicSharedMemorySize, SMEM_BYTES);
    cudaFuncSetAttribute(gnn_gemm<2>, cudaFuncAttributeMaxDynamicSharedMemorySize, SMEM_BYTES);

    const int M1 = B * NO;   // 32768
    const int M2 = B * NR;   // 65536
    gnn_gemm<1><<<dim3(DIM/BN, M1/BM), 256, SMEM_BYTES>>>(
        objh, attrh, attr, nullptr, nullptr, wah, ba, out + objN);
    gnn_gemm<2><<<dim3(DIM/BN, M2/BM), 256, SMEM_BYTES>>>(
        objh, relah, rela, edges, masks, wrh, br, out + 2*objN);
}